// round 4
// baseline (speedup 1.0000x reference)
#include <cuda_runtime.h>
#include <math.h>

// Problem constants (fixed by the reference)
#define T_DIM 1600
#define N_DIM 32
#define C_DIM 512
#define S_DIM 200
#define L_DIM (2 * S_DIM + 1)   // 401 extended states
#define NEGF  (-1e30f)
#define NTHREADS 416            // 13 warps, covers L_DIM=401
#define PF 4                    // emission prefetch depth (register pipeline)

// per-example normalized loss scratch (static device global: no allocs allowed)
__device__ float g_per_ex[N_DIM];

__global__ __launch_bounds__(NTHREADS, 1)
void ctc_alpha_kernel(const float* __restrict__ log_probs,   // (T, N, C)
                      const int*   __restrict__ targets,     // (N, S)
                      const int*   __restrict__ input_lens,  // (N,)
                      const int*   __restrict__ target_lens) // (N,)
{
    // ping-pong alpha buffers, front-padded by 2 with NEG so s-1/s-2 reads
    // never branch
    __shared__ float abuf[2][L_DIM + 2];

    const int n = blockIdx.x;
    const int s = threadIdx.x;
    const bool act = (s < L_DIM);
    const int inlen = input_lens[n];
    const int tlen  = target_lens[n];

    // extended label for this state + skip-transition permission
    int ext = 0;            // blank for even s
    bool skip = false;
    if (act && (s & 1)) {
        const int li = s >> 1;               // (s-1)/2 for odd s
        ext = targets[n * S_DIM + li];
        // skip allowed: s>=2, non-blank (odd always non-blank here),
        // and differs from ext[s-2] = targets[li-1]
        skip = (s >= 2) && (ext != targets[n * S_DIM + li - 1]);
    }

    const float* base = log_probs + (size_t)n * C_DIM + ext;
    const int stride = N_DIM * C_DIM;        // 16384 floats per timestep

    // init alpha(t=0)
    if (s < 2) { abuf[0][s] = NEGF; abuf[1][s] = NEGF; }
    if (act) {
        const float e0 = __ldg(base);        // log_probs[0][n][ext]
        float a0 = NEGF;
        if (s == 0) a0 = e0;
        else if (s == 1) a0 = (tlen >= 1) ? e0 : NEGF;
        abuf[0][s + 2] = a0;
    }

    // depth-PF emission prefetch pipeline (addresses valid via clamp; extra
    // values never consumed)
    float e[PF];
#pragma unroll
    for (int i = 0; i < PF; ++i) {
        const int t = 1 + i;
        e[i] = act ? __ldg(base + (size_t)((t < T_DIM) ? t : (T_DIM - 1)) * stride)
                   : NEGF;
    }
    __syncthreads();

    int cur = 0;
    for (int t = 1; t < T_DIM; ++t) {
        const float emit = e[0];
#pragma unroll
        for (int i = 0; i < PF - 1; ++i) e[i] = e[i + 1];
        {
            const int tp = t + PF;
            const int tc = (tp < T_DIM) ? tp : (T_DIM - 1);
            if (act) e[PF - 1] = __ldg(base + (size_t)tc * stride);
        }

        const int nxt = cur ^ 1;
        if (act) {
            const float a  = abuf[cur][s + 2];
            const float a1 = abuf[cur][s + 1];
            const float a2 = skip ? abuf[cur][s] : NEGF;

            // 3-way logsumexp with the max-term folded to exp(0)=1.
            // Median via min/max network (NOT the sum trick: -1e30 sentinels
            // catastrophically cancel there).
            const float mx1 = fmaxf(a, a1);
            const float mn1 = fminf(a, a1);
            const float m   = fmaxf(mx1, a2);
            const float md  = fmaxf(mn1, fminf(mx1, a2));
            const float mn  = fminf(mn1, a2);

            const float sum = 1.0f + __expf(md - m) + __expf(mn - m);
            const float nv  = m + __logf(sum) + emit;
            // freeze trellis past input_len (reference semantics)
            abuf[nxt][s + 2] = (t < inlen) ? nv : a;
        }
        cur = nxt;
        __syncthreads();
    }

    if (s == 0) {
        const int il = 2 * tlen;                       // final blank state
        const float al = abuf[cur][il + 2];
        const float ap = (tlen > 0) ? abuf[cur][il + 1] : NEGF;
        const float m  = fmaxf(al, ap);
        float per = -(m + __logf(__expf(al - m) + __expf(ap - m)));
        per = (per < 1e29f) ? per : 0.0f;              // zero_infinity
        const float norm = sqrtf(fmaxf((float)tlen, 1.0f));  // ALPHA = 0.5
        g_per_ex[n] = per / norm;
    }
}

__global__ void ctc_reduce_kernel(float* __restrict__ out)
{
    float v = g_per_ex[threadIdx.x];     // exactly N_DIM=32 threads
#pragma unroll
    for (int o = 16; o > 0; o >>= 1)
        v += __shfl_xor_sync(0xffffffffu, v, o);
    if (threadIdx.x == 0) out[0] = v / (float)N_DIM;
}

extern "C" void kernel_launch(void* const* d_in, const int* in_sizes, int n_in,
                              void* d_out, int out_size)
{
    const float* log_probs   = (const float*)d_in[0];
    const int*   targets     = (const int*)  d_in[1];
    const int*   input_lens  = (const int*)  d_in[2];
    const int*   target_lens = (const int*)  d_in[3];

    ctc_alpha_kernel<<<N_DIM, NTHREADS>>>(log_probs, targets, input_lens, target_lens);
    ctc_reduce_kernel<<<1, 32>>>((float*)d_out);
}

// round 7
// speedup vs baseline: 3.1884x; 3.1884x over previous
#include <cuda_runtime.h>
#include <math.h>

// Problem constants (fixed by the reference)
#define T_DIM 1600
#define N_DIM 32
#define C_DIM 512
#define S_DIM 200
#define L_DIM (2 * S_DIM + 1)   // 401 extended states
#define NEGF  (-1e30f)
#define NTHREADS 416            // 13 warps, covers L_DIM=401
#define STAGES 8                // SMEM emission-row ring (power of 2)
#define PF 6                    // prefetch distance in timesteps (<= STAGES-1)

// per-example normalized loss scratch (static device global: no allocs allowed)
__device__ float g_per_ex[N_DIM];

__device__ __forceinline__ void cp_async16(void* smem_dst, const void* gmem_src) {
    unsigned s = (unsigned)__cvta_generic_to_shared(smem_dst);
    asm volatile("cp.async.cg.shared.global [%0], [%1], 16;\n" :: "r"(s), "l"(gmem_src));
}
__device__ __forceinline__ void cp_commit() {
    asm volatile("cp.async.commit_group;\n");
}
template <int N>
__device__ __forceinline__ void cp_wait() {
    asm volatile("cp.async.wait_group %0;\n" :: "n"(N));
}

__global__ __launch_bounds__(NTHREADS, 1)
void ctc_alpha_kernel(const float* __restrict__ log_probs,   // (T, N, C)
                      const int*   __restrict__ targets,     // (N, S)
                      const int*   __restrict__ input_lens,  // (N,)
                      const int*   __restrict__ target_lens) // (N,)
{
    // emission-row staging ring: 8 stages x 512 floats = 16 KB.
    // MUST be 16B-aligned: cp.async.16 traps on misaligned SMEM dst
    // (R5 failure: this sat after abuf, whose 3224-byte size left it 8 mod 16).
    __shared__ __align__(16) float stage[STAGES][C_DIM];
    // ping-pong alpha, front-padded by 2 with NEG so s-1/s-2 reads never branch
    __shared__ __align__(16) float abuf[2][L_DIM + 2];

    const int n = blockIdx.x;
    const int s = threadIdx.x;
    const bool act = (s < L_DIM);
    const int inlen = input_lens[n];
    const int tlen  = target_lens[n];

    // extended label for this state + skip-transition permission
    int ext = 0;            // blank for even s
    bool skip = false;
    if (act && (s & 1)) {
        const int li = s >> 1;               // (s-1)/2 for odd s
        ext = targets[n * S_DIM + li];
        skip = (s >= 2) && (ext != targets[n * S_DIM + li - 1]);
    }

    const int stride = N_DIM * C_DIM;                         // floats per timestep
    const float* row0 = log_probs + (size_t)n * C_DIM;        // row for t=0

    // coalesced-copy source pointer for this thread (tid<128 copy 16B each)
    const float* cp_src = row0 + s * 4;
    const bool   cp_on  = (s < C_DIM / 4);                    // 128 copier threads

    // init alpha(t=0) — one-time scattered gather, cost irrelevant
    if (s < 2) { abuf[0][s] = NEGF; abuf[1][s] = NEGF; }
    if (act) {
        const float e0 = __ldg(row0 + ext);
        float a0 = NEGF;
        if (s == 0) a0 = e0;
        else if (s == 1) a0 = (tlen >= 1) ? e0 : NEGF;
        abuf[0][s + 2] = a0;
    }

    // prologue: prefetch rows for t = 1..PF into stages 1..PF
#pragma unroll
    for (int t = 1; t <= PF; ++t) {
        if (cp_on) cp_async16(&stage[t & (STAGES - 1)][s * 4],
                              cp_src + (size_t)t * stride);
        cp_commit();   // ALL threads commit (empty groups keep counts aligned)
    }
    __syncthreads();

    int cur = 0;
    for (int t = 1; t < T_DIM; ++t) {
        // oldest pending group = row for this t
        cp_wait<PF - 1>();
        __syncthreads();   // publishes stage[t] to all warps AND alpha[t-1]

        const int nxt = cur ^ 1;
        if (act) {
            const float emit = stage[t & (STAGES - 1)][ext];   // LDS gather
            const float a  = abuf[cur][s + 2];
            const float a1 = abuf[cur][s + 1];
            const float a2 = skip ? abuf[cur][s] : NEGF;

            // 3-way logsumexp, max folded to exp(0)=1; median via min/max
            // network (sum trick catastrophically cancels with -1e30)
            const float mx1 = fmaxf(a, a1);
            const float mn1 = fminf(a, a1);
            const float m   = fmaxf(mx1, a2);
            const float md  = fmaxf(mn1, fminf(mx1, a2));
            const float mn  = fminf(mn1, a2);

            const float sum = 1.0f + __expf(md - m) + __expf(mn - m);
            const float nv  = m + __logf(sum) + emit;
            abuf[nxt][s + 2] = (t < inlen) ? nv : a;   // freeze past input_len
        }
        cur = nxt;

        // prefetch row for t+PF (stage last read >= 2 barriers ago: safe)
        const int tp = t + PF;
        if (tp < T_DIM && cp_on)
            cp_async16(&stage[tp & (STAGES - 1)][s * 4],
                       cp_src + (size_t)tp * stride);
        cp_commit();
    }
    __syncthreads();

    if (s == 0) {
        const int il = 2 * tlen;                       // final blank state
        const float al = abuf[cur][il + 2];
        const float ap = (tlen > 0) ? abuf[cur][il + 1] : NEGF;
        const float m  = fmaxf(al, ap);
        float per = -(m + __logf(__expf(al - m) + __expf(ap - m)));
        per = (per < 1e29f) ? per : 0.0f;              // zero_infinity
        const float norm = sqrtf(fmaxf((float)tlen, 1.0f));  // ALPHA = 0.5
        g_per_ex[n] = per / norm;
    }
}

__global__ void ctc_reduce_kernel(float* __restrict__ out)
{
    float v = g_per_ex[threadIdx.x];     // exactly N_DIM=32 threads
#pragma unroll
    for (int o = 16; o > 0; o >>= 1)
        v += __shfl_xor_sync(0xffffffffu, v, o);
    if (threadIdx.x == 0) out[0] = v / (float)N_DIM;
}

extern "C" void kernel_launch(void* const* d_in, const int* in_sizes, int n_in,
                              void* d_out, int out_size)
{
    const float* log_probs   = (const float*)d_in[0];
    const int*   targets     = (const int*)  d_in[1];
    const int*   input_lens  = (const int*)  d_in[2];
    const int*   target_lens = (const int*)  d_in[3];

    ctc_alpha_kernel<<<N_DIM, NTHREADS>>>(log_probs, targets, input_lens, target_lens);
    ctc_reduce_kernel<<<1, 32>>>((float*)d_out);
}

// round 10
// speedup vs baseline: 3.9715x; 1.2456x over previous
#include <cuda_runtime.h>
#include <math.h>

// Problem constants (fixed by the reference)
#define T_DIM 1600
#define N_DIM 32
#define C_DIM 512
#define S_DIM 200
#define L_DIM (2 * S_DIM + 1)   // 401 extended states
#define NEGF  (-1e30f)
#define PAIRS 201               // thread k owns states (2k, 2k+1); k=200 even-only
#define NTHREADS 224            // 7 warps
#define STAGES 8                // SMEM emission-row ring (power of 2)
#define PF 6                    // prefetch distance in timesteps (<= STAGES-1)

// per-example normalized loss scratch (static device global: no allocs allowed)
__device__ float g_per_ex[N_DIM];

__device__ __forceinline__ void cp_async16(void* smem_dst, const void* gmem_src) {
    unsigned s = (unsigned)__cvta_generic_to_shared(smem_dst);
    asm volatile("cp.async.cg.shared.global [%0], [%1], 16;\n" :: "r"(s), "l"(gmem_src));
}
__device__ __forceinline__ void cp_commit() {
    asm volatile("cp.async.commit_group;\n");
}
template <int N>
__device__ __forceinline__ void cp_wait() {
    asm volatile("cp.async.wait_group %0;\n" :: "n"(N));
}

__global__ __launch_bounds__(NTHREADS, 1)
void ctc_alpha_kernel(const float* __restrict__ log_probs,   // (T, N, C)
                      const int*   __restrict__ targets,     // (N, S)
                      const int*   __restrict__ input_lens,  // (N,)
                      const int*   __restrict__ target_lens) // (N,)
{
    // emission-row staging ring. 16B alignment mandatory for cp.async.16 (R5).
    __shared__ __align__(16) float stage[STAGES][C_DIM];
    // ping-pong ODD-state alphas, shifted by 1: obuf[b][k+1] = alpha[2k+1],
    // obuf[b][0] = NEG (virtual alpha[-1]) so thread k reads alpha[2k-1] at [k]
    __shared__ __align__(16) float obuf[2][PAIRS + 1];
    __shared__ float ebuf[PAIRS];   // final even alphas for readout

    const int n = blockIdx.x;
    const int k = threadIdx.x;
    const bool has_e = (k <= PAIRS - 1);   // even state 2k exists (k<=200)
    const bool has_o = (k <  S_DIM);       // odd state 2k+1 exists (k<=199)
    const int kc = (k < PAIRS) ? k : (PAIRS - 1);  // clamped SMEM index
    const int inlen = input_lens[n];
    const int tlen  = target_lens[n];

    // label for odd state 2k+1 + skip permission
    int ext = 0;
    bool skip = false;
    if (has_o) {
        ext = targets[n * S_DIM + k];
        skip = (k >= 1) && (ext != targets[n * S_DIM + k - 1]);
    }

    const int stride = N_DIM * C_DIM;                  // floats per timestep
    const float* row0 = log_probs + (size_t)n * C_DIM; // row for t=0

    // coalesced copier: 128 threads x 16B = full 2KB row
    const float* cp_src = row0 + k * 4;
    const bool   cp_on  = (k < C_DIM / 4);

    // init alpha(t=0): only s=0 and s=1 feasible
    float ae = NEGF, ao = NEGF;
    if (k == 0) {
        ae = __ldg(row0 + 0);                              // blank
        ao = (tlen >= 1) ? __ldg(row0 + ext) : NEGF;       // first label
        obuf[0][0] = NEGF; obuf[1][0] = NEGF;              // virtual alpha[-1]
    }
    if (has_o) obuf[0][k + 1] = ao;

    // prologue: prefetch rows for t = 1..PF
#pragma unroll
    for (int t = 1; t <= PF; ++t) {
        if (cp_on) cp_async16(&stage[t & (STAGES - 1)][k * 4],
                              cp_src + (size_t)t * stride);
        cp_commit();   // all threads commit (keeps group counts aligned)
    }
    __syncthreads();

    int cur = 0;
    for (int t = 1; t < T_DIM; ++t) {
        cp_wait<PF - 1>();
        __syncthreads();   // publishes stage[t] and obuf[cur]

        const float* st = stage[t & (STAGES - 1)];
        const float eb  = st[0];      // blank emission: broadcast LDS
        const float el  = st[ext];    // label emission: gather LDS
        const float am1 = obuf[cur][kc];   // alpha[2k-1] (old)

        // even state 2k: LSE2(ae, am1) + eb   (blank never skips)
        const float m1  = fmaxf(ae, am1);
        const float mn1 = fminf(ae, am1);
        float ne = m1 + __logf(1.0f + __expf(mn1 - m1)) + eb;

        // odd state 2k+1: LSE3(ao, ae, skip ? am1 : NEG) + el
        const float a2  = skip ? am1 : NEGF;
        const float mxA = fmaxf(ao, ae);
        const float mnA = fminf(ao, ae);
        const float m   = fmaxf(mxA, a2);
        const float md  = fmaxf(mnA, fminf(mxA, a2));
        const float mn  = fminf(mnA, a2);
        float no = m + __logf(1.0f + __expf(md - m) + __expf(mn - m)) + el;

        // freeze past input_len (reference semantics)
        ne = (t < inlen) ? ne : ae;
        no = (t < inlen) ? no : ao;

        const int nxt = cur ^ 1;
        if (has_e) ae = ne;
        if (has_o) { ao = no; obuf[nxt][k + 1] = no; }
        cur = nxt;

        // prefetch row for t+PF (slot last read >= 2 barriers ago: safe)
        const int tp = t + PF;
        if (tp < T_DIM && cp_on)
            cp_async16(&stage[tp & (STAGES - 1)][k * 4],
                       cp_src + (size_t)tp * stride);
        cp_commit();
    }
    __syncthreads();
    if (has_e) ebuf[k] = ae;
    __syncthreads();

    if (k == 0) {
        // a_last = alpha[2*tlen] (even, pair tlen); a_prev = alpha[2*tlen-1]
        const float al = ebuf[tlen];
        const float ap = (tlen > 0) ? obuf[cur][tlen] : NEGF;
        const float m  = fmaxf(al, ap);
        float per = -(m + __logf(__expf(al - m) + __expf(ap - m)));
        per = (per < 1e29f) ? per : 0.0f;              // zero_infinity
        const float norm = sqrtf(fmaxf((float)tlen, 1.0f));  // ALPHA = 0.5
        g_per_ex[n] = per / norm;
    }
}

__global__ void ctc_reduce_kernel(float* __restrict__ out)
{
    float v = g_per_ex[threadIdx.x];     // exactly N_DIM=32 threads
#pragma unroll
    for (int o = 16; o > 0; o >>= 1)
        v += __shfl_xor_sync(0xffffffffu, v, o);
    if (threadIdx.x == 0) out[0] = v / (float)N_DIM;
}

extern "C" void kernel_launch(void* const* d_in, const int* in_sizes, int n_in,
                              void* d_out, int out_size)
{
    const float* log_probs   = (const float*)d_in[0];
    const int*   targets     = (const int*)  d_in[1];
    const int*   input_lens  = (const int*)  d_in[2];
    const int*   target_lens = (const int*)  d_in[3];

    ctc_alpha_kernel<<<N_DIM, NTHREADS>>>(log_probs, targets, input_lens, target_lens);
    ctc_reduce_kernel<<<1, 32>>>((float*)d_out);
}